// round 13
// baseline (speedup 1.0000x reference)
#include <cuda_runtime.h>
#include <math.h>
#include <stdint.h>

#define BATCH 8
#define CIN   256
#define NPOS  1568
#define NH    4
#define DH    128
#define O3    1536
#define NT    25

// Scratch layouts:
//  pi(k) = ((k&3)<<2)|((k>>2)&3)           (d-dim of Q/K, 16-groups)
//  rho(j) = 4*((j>>1)&3) + 2*(j>>3) + (j&1) (tok-dim of V, 16-groups)
__device__ float g_q[BATCH*NH*NPOS*DH];   // [bh][tok][pi(d)], *scl*log2e, tf32
__device__ float g_k[BATCH*NH*NPOS*DH];   // [bh][tok][pi(d)], emb folded, tf32
__device__ float g_v[BATCH*NH*DH*NPOS];   // [bh][d][rho(tok)], tf32
__device__ float g_wh[O3*CIN];            // tf32(W)
__device__ float g_wl[O3*CIN];            // tf32(W - tf32(W))

__device__ __forceinline__ float to_tf32(float x) {
    uint32_t u; asm("cvt.rna.tf32.f32 %0, %1;" : "=r"(u) : "f"(x));
    return __uint_as_float(u);
}
__device__ __forceinline__ float fast_exp2(float x) {
    float y; asm("ex2.approx.f32 %0, %1;" : "=f"(y) : "f"(x)); return y;
}
__device__ __forceinline__ void mma_tf32(float c[4],
        uint32_t a0, uint32_t a1, uint32_t a2, uint32_t a3,
        uint32_t b0, uint32_t b1) {
    asm volatile(
        "mma.sync.aligned.m16n8k8.row.col.f32.tf32.tf32.f32 "
        "{%0,%1,%2,%3}, {%4,%5,%6,%7}, {%8,%9}, {%0,%1,%2,%3};\n"
        : "+f"(c[0]), "+f"(c[1]), "+f"(c[2]), "+f"(c[3])
        : "r"(a0), "r"(a1), "r"(a2), "r"(a3), "r"(b0), "r"(b1));
}
__device__ __forceinline__ void cp16(uint32_t dst, const void* src, bool ok) {
    unsigned sz = ok ? 16u : 0u;
    asm volatile("cp.async.cg.shared.global [%0], [%1], 16, %2;\n"
                 :: "r"(dst), "l"(src), "r"(sz));
}
#define CP_COMMIT()  asm volatile("cp.async.commit_group;\n")
#define CP_WAIT(N)   asm volatile("cp.async.wait_group %0;\n" :: "n"(N))

// ---------------------------------------------------------------------------
// Kernel W: one-time hi/lo tf32 split of W_qkv.
// ---------------------------------------------------------------------------
__global__ __launch_bounds__(256) void wsplit_kernel(const float* __restrict__ Wq)
{
    int idx = (blockIdx.x * 256 + threadIdx.x) * 4;
    float4 v = *(const float4*)&Wq[idx];
    float hx = to_tf32(v.x), hy = to_tf32(v.y), hz = to_tf32(v.z), hw = to_tf32(v.w);
    *(float4*)&g_wh[idx] = make_float4(hx, hy, hz, hw);
    *(float4*)&g_wl[idx] = make_float4(to_tf32(v.x-hx), to_tf32(v.y-hy),
                                       to_tf32(v.z-hz), to_tf32(v.w-hw));
}

// ---------------------------------------------------------------------------
// Kernel A: QKV projection via 3xTF32 compensated mma GEMM (round-12 design).
// ---------------------------------------------------------------------------
__global__ __launch_bounds__(128) void qkv_kernel(
    const float* __restrict__ fmap,
    const float* __restrict__ pf, const float* __restrict__ ph,
    const float* __restrict__ pw)
{
    extern __shared__ float qsm[];
    float* Bh = qsm + 16384;
    float* Bl = qsm + 20480;
    float* Ts = qsm;

    const int tid  = threadIdx.x;
    const int lane = tid & 31, w = tid >> 5;
    const int gid  = lane >> 2, tig = lane & 3;
    const int row0 = w*16 + gid;
    const int pbase = blockIdx.x * 64;
    const int obase = blockIdx.y * 64;
    const int b     = blockIdx.z;
    const int g4 = gid & 4, g3 = gid & 3, tsw = tig << 3, ksw = gid << 2;
    const int r0 = tid >> 4, c4l = (tid & 15) * 4;
    const uint32_t sbase = (uint32_t)__cvta_generic_to_shared(qsm);

    float acc[8][4];
#pragma unroll
    for (int nb=0;nb<8;nb++)
#pragma unroll
        for (int c=0;c<4;c++) acc[nb][c] = 0.f;

    auto loadA = [&](int ks, int buf) {
        uint32_t dA = sbase + (uint32_t)buf * 32768u;
#pragma unroll
        for (int p=0;p<8;p++) {
            int r = r0 + p*8;
            uint32_t o = (uint32_t)(r*64 + (c4l ^ ((r&7)<<2))) * 4u;
            cp16(dA + o,          &g_wh[(obase + r)*CIN + ks*64 + c4l], true);
            cp16(dA + 16384u + o, &g_wl[(obase + r)*CIN + ks*64 + c4l], true);
        }
    };

    float4 rb[8];
    loadA(0, 0); CP_COMMIT();
#pragma unroll
    for (int p=0;p<8;p++) {
        int r = r0 + p*8;
        rb[p] = make_float4(0.f,0.f,0.f,0.f);
        if (pbase + c4l < NPOS)
            rb[p] = *(const float4*)&fmap[(size_t)(b*CIN + r)*NPOS + pbase + c4l];
    }

    for (int ks = 0; ks < 4; ks++) {
#pragma unroll
        for (int p=0;p<8;p++) {
            int r = r0 + p*8;
            float4 v = rb[p];
            float hx = to_tf32(v.x), hy = to_tf32(v.y), hz = to_tf32(v.z), hw = to_tf32(v.w);
            int o = r*64 + (c4l ^ ((r&3)<<3));
            *(float4*)&Bh[o] = make_float4(hx, hy, hz, hw);
            *(float4*)&Bl[o] = make_float4(to_tf32(v.x-hx), to_tf32(v.y-hy),
                                           to_tf32(v.z-hz), to_tf32(v.w-hw));
        }
        CP_WAIT(0);
        __syncthreads();

        if (ks < 3) {
            loadA(ks+1, (ks+1)&1); CP_COMMIT();
            int kn = (ks+1)*64;
#pragma unroll
            for (int p=0;p<8;p++) {
                int r = r0 + p*8;
                rb[p] = make_float4(0.f,0.f,0.f,0.f);
                if (pbase + c4l < NPOS)
                    rb[p] = *(const float4*)&fmap[(size_t)(b*CIN + kn + r)*NPOS + pbase + c4l];
            }
        }

        const float* Ah = qsm + (ks&1)*8192;
        const float* Al = Ah + 4096;
#pragma unroll
        for (int kc=0; kc<8; kc++) {
            int k0 = kc*8;
            uint32_t ah0 = __float_as_uint(Ah[ row0   *64 + (k0^ksw) + tig]);
            uint32_t ah1 = __float_as_uint(Ah[(row0+8)*64 + (k0^ksw) + tig]);
            uint32_t ah2 = __float_as_uint(Ah[ row0   *64 + ((k0+4)^ksw) + tig]);
            uint32_t ah3 = __float_as_uint(Ah[(row0+8)*64 + ((k0+4)^ksw) + tig]);
            uint32_t al0 = __float_as_uint(Al[ row0   *64 + (k0^ksw) + tig]);
            uint32_t al1 = __float_as_uint(Al[(row0+8)*64 + (k0^ksw) + tig]);
            uint32_t al2 = __float_as_uint(Al[ row0   *64 + ((k0+4)^ksw) + tig]);
            uint32_t al3 = __float_as_uint(Al[(row0+8)*64 + ((k0+4)^ksw) + tig]);
#pragma unroll
            for (int nb=0; nb<8; nb++) {
                int cA = ((nb*8+g4)^tsw) + g3;
                uint32_t bh0 = __float_as_uint(Bh[(k0+tig  )*64 + cA]);
                uint32_t bh1 = __float_as_uint(Bh[(k0+tig+4)*64 + cA]);
                uint32_t bl0 = __float_as_uint(Bl[(k0+tig  )*64 + cA]);
                uint32_t bl1 = __float_as_uint(Bl[(k0+tig+4)*64 + cA]);
                mma_tf32(acc[nb], ah0,ah1,ah2,ah3, bl0,bl1);
                mma_tf32(acc[nb], al0,al1,al2,al3, bh0,bh1);
                mma_tf32(acc[nb], ah0,ah1,ah2,ah3, bh0,bh1);
            }
        }
        __syncthreads();
    }

    const float scl = 0.08838834764831845f * 1.4426950408889634f;
    const int sec  = obase >> 9;
    const int head = (obase >> 7) & 3;
    const int d0   = obase & 127;
    const int bh   = b*NH + head;

    if (sec < 2) {
#pragma unroll
        for (int nb=0;nb<8;nb++)
#pragma unroll
            for (int half=0;half<2;half++)
#pragma unroll
                for (int e=0;e<2;e++)
                    Ts[(nb*8 + 2*tig + e)*65 + row0 + half*8] = acc[nb][half*2+e];
    } else {
#pragma unroll
        for (int nb=0;nb<8;nb++)
#pragma unroll
            for (int half=0;half<2;half++)
#pragma unroll
                for (int e=0;e<2;e++)
                    Ts[(row0 + half*8)*65 + nb*8 + 2*tig + e] = acc[nb][half*2+e];
    }
    __syncthreads();

    const int rr  = tid >> 4;
    const int c4  = (tid & 15) * 4;
    const int tq  = (c4 >> 2) & 3;
    const int cb  = c4 & ~15;
    const int lc0 = cb + tq, lc1 = cb + 4 + tq, lc2 = cb + 8 + tq, lc3 = cb + 12 + tq;
    const int lv0 = cb + 2*tq, lv1 = cb + 2*tq + 1, lv2 = cb + 2*tq + 8, lv3 = cb + 2*tq + 9;

#pragma unroll
    for (int pass=0; pass<8; pass++) {
        int r = rr + pass*8;
        if (sec == 2) {
            if (pbase + c4 < NPOS) {
                float v0 = Ts[r*65+lv0], v1 = Ts[r*65+lv1];
                float v2 = Ts[r*65+lv2], v3 = Ts[r*65+lv3];
                *(float4*)&g_v[((size_t)bh*DH + d0 + r)*NPOS + pbase + c4] =
                    make_float4(to_tf32(v0), to_tf32(v1), to_tf32(v2), to_tf32(v3));
            }
        } else {
            float v0 = Ts[r*65+lc0], v1 = Ts[r*65+lc1];
            float v2 = Ts[r*65+lc2], v3 = Ts[r*65+lc3];
            int pos = pbase + r;
            if (pos < NPOS) {
                size_t o_ = ((size_t)bh*NPOS + pos)*DH + d0 + c4;
                if (sec == 0) {
                    *(float4*)&g_q[o_] = make_float4(
                        to_tf32(v0*scl), to_tf32(v1*scl), to_tf32(v2*scl), to_tf32(v3*scl));
                } else {
                    int f_ = pos / 196; int rem = pos - f_*196;
                    int h_ = rem / 14;  int w_  = rem - h_*14;
                    const float* pfr = pf + f_*DH + d0;
                    const float* phr = ph + h_*DH + d0;
                    const float* pwr = pw + w_*DH + d0;
                    *(float4*)&g_k[o_] = make_float4(
                        to_tf32(v0 + pfr[lc0] + phr[lc0] + pwr[lc0]),
                        to_tf32(v1 + pfr[lc1] + phr[lc1] + pwr[lc1]),
                        to_tf32(v2 + pfr[lc2] + phr[lc2] + pwr[lc2]),
                        to_tf32(v3 + pfr[lc3] + phr[lc3] + pwr[lc3]));
                }
            }
        }
    }
}

// ---------------------------------------------------------------------------
// Kernel B: flash attention, Br=128/CTA, software-pipelined:
// iter t: S(t) mma, then PV(t-1) mma INTERLEAVED with softmax(t) — the 512
// MUFU cycles of exp2 hide under the PV tensor block. Q frags from smem
// (frees regs for ping-pong S). K & V double-buffered; ONE sync per tile.
// ---------------------------------------------------------------------------
__global__ __launch_bounds__(256, 1) void attn_kernel(float* __restrict__ out)
{
    extern __shared__ float sm[];
    float* Qs  = sm;                    // 128 x 128 swizzled
    float* Kbuf0 = sm + 16384;
    float* Kbuf1 = sm + 24576;
    float* Vbuf0 = sm + 32768;
    float* Vbuf1 = sm + 40960;
    float* Od  = sm;                    // 128 x 132 epilogue overlay

    const int tid  = threadIdx.x;
    const int lane = tid & 31, w = tid >> 5;
    const int gid  = lane >> 2, tig = lane & 3;
    const int qt = blockIdx.x, bh = blockIdx.y;
    const int qbase = qt * 128;
    const int row0 = w*16 + gid;        // 0..127
    const int gsw = gid << 4;
    const int vsw = (gid & 3) << 4;

    const float* qp = g_q + (size_t)bh * NPOS * DH;
    const float* kp = g_k + (size_t)bh * NPOS * DH;
    const float* vp = g_v + (size_t)bh * DH * NPOS;

    const uint32_t smQ  = (uint32_t)__cvta_generic_to_shared(Qs);
    const uint32_t smK0 = (uint32_t)__cvta_generic_to_shared(Kbuf0);
    const uint32_t smK1 = (uint32_t)__cvta_generic_to_shared(Kbuf1);
    const uint32_t smV0 = (uint32_t)__cvta_generic_to_shared(Vbuf0);
    const uint32_t smV1 = (uint32_t)__cvta_generic_to_shared(Vbuf1);

    // ---- prologue: cp.async Q (full 128x128), K(0), V(0) ----
#pragma unroll
    for (int p=0;p<16;p++) {
        int idx = p*256 + tid;
        int r = idx >> 5, c4 = (idx & 31) * 4;
        cp16(smQ + (r*128 + (c4 ^ ((r&7)<<4)))*4,
             &qp[(size_t)(qbase + r)*DH + c4], qbase + r < NPOS);
        if (qbase + r >= NPOS)
            *(float4*)&Qs[r*128 + (c4 ^ ((r&7)<<4))] = make_float4(0.f,0.f,0.f,0.f);
    }
    CP_COMMIT();
#pragma unroll
    for (int p=0;p<8;p++) {
        int idx = p*256 + tid;
        int r = idx >> 5, c4 = (idx & 31) * 4;
        cp16(smK0 + (r*128 + (c4 ^ ((r&7)<<4)))*4, &kp[(size_t)r*DH + c4], r < NPOS);
    }
    CP_COMMIT();
#pragma unroll
    for (int p=0;p<8;p++) {
        int idx = p*256 + tid;
        int r = idx >> 4, c4 = (idx & 15) * 4;
        cp16(smV0 + (r*64 + (c4 ^ ((r&3)<<4)))*4, &vp[(size_t)r*NPOS + c4], c4 < NPOS);
    }
    CP_COMMIT();

    float m0 = 0.f, m1 = 0.f, l0 = 0.f, l1 = 0.f;
    float Sa[8][4], Sb[8][4], O[16][4];
#pragma unroll
    for (int nb=0;nb<16;nb++)
#pragma unroll
        for (int c=0;c<4;c++) O[nb][c] = 0.f;

    // ---- per-iteration macro ----
#define PREFETCH_KV(T_) do { \
    if ((T_) < NT-1) { \
        int tn = (T_)+1; \
        const float* kpn = kp + (size_t)tn*64*DH; \
        uint32_t dstK = (tn & 1) ? smK1 : smK0; \
        _Pragma("unroll") \
        for (int p=0;p<8;p++) { \
            int idx = p*256 + tid; \
            int r = idx >> 5, c4 = (idx & 31) * 4; \
            cp16(dstK + (r*128 + (c4 ^ ((r&7)<<4)))*4, \
                 &kpn[(size_t)r*DH + c4], tn*64 + r < NPOS); \
        } \
        CP_COMMIT(); \
    } \
    if ((T_) >= 1) { \
        int tv = (T_); \
        const float* vpn = vp + (size_t)tv*64; \
        uint32_t dstV = (tv & 1) ? smV1 : smV0; \
        _Pragma("unroll") \
        for (int p=0;p<8;p++) { \
            int idx = p*256 + tid; \
            int r = idx >> 4, c4 = (idx & 15) * 4; \
            cp16(dstV + (r*64 + (c4 ^ ((r&3)<<4)))*4, \
                 &vpn[(size_t)r*NPOS + c4], tv*64 + c4 < NPOS); \
        } \
        CP_COMMIT(); \
    } \
} while (0)

#define S_PHASE(T_, SC) do { \
    const float* Ks_ = ((T_) & 1) ? Kbuf1 : Kbuf0; \
    _Pragma("unroll") \
    for (int nb=0;nb<8;nb++) \
        _Pragma("unroll") \
        for (int c=0;c<4;c++) SC[nb][c] = 0.f; \
    _Pragma("unroll") \
    for (int kpi=0;kpi<8;kpi++) { \
        float4 q0 = *(const float4*)&Qs[ row0   *128 + ((kpi*16) ^ gsw) + tig*4]; \
        float4 q1 = *(const float4*)&Qs[(row0+8)*128 + ((kpi*16) ^ gsw) + tig*4]; \
        uint32_t e0=__float_as_uint(q0.x), e1=__float_as_uint(q1.x); \
        uint32_t e2=__float_as_uint(q0.y), e3=__float_as_uint(q1.y); \
        uint32_t o0=__float_as_uint(q0.z), o1=__float_as_uint(q1.z); \
        uint32_t o2=__float_as_uint(q0.w), o3=__float_as_uint(q1.w); \
        _Pragma("unroll") \
        for (int nb=0;nb<8;nb++) { \
            int rr = nb*8 + gid; \
            float4 kv = *(const float4*)&Ks_[rr*128 + ((kpi*16) ^ gsw) + tig*4]; \
            mma_tf32(SC[nb], e0,e1,e2,e3, __float_as_uint(kv.x), __float_as_uint(kv.y)); \
            mma_tf32(SC[nb], o0,o1,o2,o3, __float_as_uint(kv.z), __float_as_uint(kv.w)); \
        } \
    } \
    if ((T_) == NT-1) { \
        _Pragma("unroll") \
        for (int nb=0;nb<8;nb++) { \
            int c0 = (T_)*64 + nb*8 + 2*tig; \
            if (c0     >= NPOS) { SC[nb][0] = -1e30f; SC[nb][2] = -1e30f; } \
            if (c0 + 1 >= NPOS) { SC[nb][1] = -1e30f; SC[nb][3] = -1e30f; } \
        } \
    } \
} while (0)

#define SOFTMAX_CHUNK(SC, J) do { \
    float p0 = fast_exp2(SC[J][0] - m0); l0 += p0; SC[J][0] = to_tf32(p0); \
    float p1 = fast_exp2(SC[J][1] - m0); l0 += p1; SC[J][1] = to_tf32(p1); \
    float p2 = fast_exp2(SC[J][2] - m1); l1 += p2; SC[J][2] = to_tf32(p2); \
    float p3 = fast_exp2(SC[J][3] - m1); l1 += p3; SC[J][3] = to_tf32(p3); \
} while (0)

#define PV_SOFTMAX(T_, SC, SP) do { \
    const float* Vs_ = (((T_)-1) & 1) ? Vbuf1 : Vbuf0; \
    _Pragma("unroll") \
    for (int kpi=0;kpi<4;kpi++) { \
        int e = 2*kpi, o = e+1; \
        uint32_t ea0 = __float_as_uint(SP[e][0]); \
        uint32_t ea1 = __float_as_uint(SP[e][2]); \
        uint32_t ea2 = __float_as_uint(SP[e][1]); \
        uint32_t ea3 = __float_as_uint(SP[e][3]); \
        uint32_t oa0 = __float_as_uint(SP[o][0]); \
        uint32_t oa1 = __float_as_uint(SP[o][2]); \
        uint32_t oa2 = __float_as_uint(SP[o][1]); \
        uint32_t oa3 = __float_as_uint(SP[o][3]); \
        _Pragma("unroll") \
        for (int nb=0;nb<16;nb++) { \
            int rr = nb*8 + gid; \
            float4 vv = *(const float4*)&Vs_[rr*64 + ((kpi*16) ^ vsw) + tig*4]; \
            mma_tf32(O[nb], ea0,ea1,ea2,ea3, __float_as_uint(vv.x), __float_as_uint(vv.y)); \
            mma_tf32(O[nb], oa0,oa1,oa2,oa3, __float_as_uint(vv.z), __float_as_uint(vv.w)); \
        } \
        SOFTMAX_CHUNK(SC, e); \
        SOFTMAX_CHUNK(SC, o); \
    } \
} while (0)

    // ---- iter 0: S(0), m_ref, softmax(0) (no PV) ----
    CP_WAIT(0); __syncthreads();
    PREFETCH_KV(0);
    S_PHASE(0, Sa);
    {
        float mx0 = -1e30f, mx1 = -1e30f;
#pragma unroll
        for (int nb=0;nb<8;nb++) {
            mx0 = fmaxf(mx0, fmaxf(Sa[nb][0], Sa[nb][1]));
            mx1 = fmaxf(mx1, fmaxf(Sa[nb][2], Sa[nb][3]));
        }
        mx0 = fmaxf(mx0, __shfl_xor_sync(0xffffffffu, mx0, 1));
        mx0 = fmaxf(mx0, __shfl_xor_sync(0xffffffffu, mx0, 2));
        mx1 = fmaxf(mx1, __shfl_xor_sync(0xffffffffu, mx1, 1));
        mx1 = fmaxf(mx1, __shfl_xor_sync(0xffffffffu, mx1, 2));
        m0 = mx0; m1 = mx1;
#pragma unroll
        for (int nb=0;nb<8;nb++) SOFTMAX_CHUNK(Sa, nb);
    }

    // ---- iters 1..24 as pairs: (odd -> Sb, even -> Sa) ----
    for (int tt = 1; tt < NT-1; tt += 2) {
        CP_WAIT(0); __syncthreads();
        PREFETCH_KV(tt);
        S_PHASE(tt, Sb);
        PV_SOFTMAX(tt, Sb, Sa);

        CP_WAIT(0); __syncthreads();
        PREFETCH_KV(tt+1);
        S_PHASE(tt+1, Sa);
        PV_SOFTMAX(tt+1, Sa, Sb);
    }

    // ---- tail: PV(24) with P in Sa, V(24) in Vbuf0 ----
    CP_WAIT(0); __syncthreads();
    {
        const float* Vs_ = Vbuf0;   // 24 & 1 == 0
#pragma unroll
        for (int kpi=0;kpi<4;kpi++) {
            int e = 2*kpi, o = e+1;
            uint32_t ea0 = __float_as_uint(Sa[e][0]);
            uint32_t ea1 = __float_as_uint(Sa[e][2]);
            uint32_t ea2 = __float_as_uint(Sa[e][1]);
            uint32_t ea3 = __float_as_uint(Sa[e][3]);
            uint32_t oa0 = __float_as_uint(Sa[o][0]);
            uint32_t oa1 = __float_as_uint(Sa[o][2]);
            uint32_t oa2 = __float_as_uint(Sa[o][1]);
            uint32_t oa3 = __float_as_uint(Sa[o][3]);
#pragma unroll
            for (int nb=0;nb<16;nb++) {
                int rr = nb*8 + gid;
                float4 vv = *(const float4*)&Vs_[rr*64 + ((kpi*16) ^ vsw) + tig*4];
                mma_tf32(O[nb], ea0,ea1,ea2,ea3, __float_as_uint(vv.x), __float_as_uint(vv.y));
                mma_tf32(O[nb], oa0,oa1,oa2,oa3, __float_as_uint(vv.z), __float_as_uint(vv.w));
            }
        }
    }

    // ---- l reduce, normalize, transpose, store ----
    l0 += __shfl_xor_sync(0xffffffffu, l0, 1);
    l0 += __shfl_xor_sync(0xffffffffu, l0, 2);
    l1 += __shfl_xor_sync(0xffffffffu, l1, 1);
    l1 += __shfl_xor_sync(0xffffffffu, l1, 2);

    __syncthreads();
    float inv0 = 1.0f / l0, inv1 = 1.0f / l1;
#pragma unroll
    for (int nb=0;nb<16;nb++) {
        Od[(nb*8 + 2*tig    )*132 + row0    ] = O[nb][0] * inv0;
        Od[(nb*8 + 2*tig + 1)*132 + row0    ] = O[nb][1] * inv0;
        Od[(nb*8 + 2*tig    )*132 + row0 + 8] = O[nb][2] * inv1;
        Od[(nb*8 + 2*tig + 1)*132 + row0 + 8] = O[nb][3] * inv1;
    }
    __syncthreads();

    const int b = bh >> 2, head = bh & 3;
    const size_t ch0 = (size_t)b*512 + head*128;
    {
        int t2 = (tid & 63) * 2;
#pragma unroll
        for (int p=0;p<32;p++) {
            int dd = (tid >> 6) + p*4;
            if (qbase + t2 < NPOS) {
                float2 v = *(const float2*)&Od[dd*132 + t2];
                *(float2*)&out[(ch0 + dd)*NPOS + qbase + t2] = v;
            }
        }
    }
#undef PREFETCH_KV
#undef S_PHASE
#undef SOFTMAX_CHUNK
#undef PV_SOFTMAX
}

// ---------------------------------------------------------------------------
extern "C" void kernel_launch(void* const* d_in, const int* in_sizes, int n_in,
                              void* d_out, int out_size)
{
    const float* fmap = (const float*)d_in[0];
    const float* Wq   = (const float*)d_in[1];
    const float* pf   = (const float*)d_in[2];
    const float* ph   = (const float*)d_in[3];
    const float* pw   = (const float*)d_in[4];
    float* out = (float*)d_out;

    wsplit_kernel<<<O3*CIN/1024, 256>>>(Wq);

    const size_t smemA = (size_t)24576 * sizeof(float);   // 96 KB
    cudaFuncSetAttribute(qkv_kernel, cudaFuncAttributeMaxDynamicSharedMemorySize,
                         (int)smemA);
    dim3 gA(25, 24, BATCH);
    qkv_kernel<<<gA, 128, smemA>>>(fmap, pf, ph, pw);

    const size_t smemB = (size_t)49152 * sizeof(float);   // 192 KB
    cudaFuncSetAttribute(attn_kernel, cudaFuncAttributeMaxDynamicSharedMemorySize,
                         (int)smemB);
    dim3 gB(13, 32);
    attn_kernel<<<gB, 256, smemB>>>(out);
}

// round 14
// speedup vs baseline: 1.0495x; 1.0495x over previous
#include <cuda_runtime.h>
#include <math.h>
#include <stdint.h>

#define BATCH 8
#define CIN   256
#define NPOS  1568
#define NH    4
#define DH    128
#define O3    1536

// Scratch layouts:
//  pi(k) = ((k&3)<<2)|((k>>2)&3)           (16-groups; d-dim of Q/K, k-dim of W)
//  rho(j) = 4*((j>>1)&3) + 2*(j>>3) + (j&1) (tok-dim of V, 16-groups)
__device__ float g_q[BATCH*NH*NPOS*DH];   // [bh][tok][pi(d)], *scl*log2e, tf32
__device__ float g_k[BATCH*NH*NPOS*DH];   // [bh][tok][pi(d)], emb folded, tf32
__device__ float g_v[BATCH*NH*DH*NPOS];   // [bh][d][rho(tok)], tf32
__device__ float g_wh[O3*CIN];            // tf32(W), pi(k) layout
__device__ float g_wl[O3*CIN];            // tf32(W - tf32(W)), pi(k) layout

__device__ __forceinline__ float to_tf32(float x) {
    uint32_t u; asm("cvt.rna.tf32.f32 %0, %1;" : "=r"(u) : "f"(x));
    return __uint_as_float(u);
}
__device__ __forceinline__ float fast_exp2(float x) {
    float y; asm("ex2.approx.f32 %0, %1;" : "=f"(y) : "f"(x)); return y;
}
__device__ __forceinline__ void mma_tf32(float c[4],
        uint32_t a0, uint32_t a1, uint32_t a2, uint32_t a3,
        uint32_t b0, uint32_t b1) {
    asm volatile(
        "mma.sync.aligned.m16n8k8.row.col.f32.tf32.tf32.f32 "
        "{%0,%1,%2,%3}, {%4,%5,%6,%7}, {%8,%9}, {%0,%1,%2,%3};\n"
        : "+f"(c[0]), "+f"(c[1]), "+f"(c[2]), "+f"(c[3])
        : "r"(a0), "r"(a1), "r"(a2), "r"(a3), "r"(b0), "r"(b1));
}
__device__ __forceinline__ void cp16(uint32_t dst, const void* src, bool ok) {
    unsigned sz = ok ? 16u : 0u;
    asm volatile("cp.async.cg.shared.global [%0], [%1], 16, %2;\n"
                 :: "r"(dst), "l"(src), "r"(sz));
}
#define CP_COMMIT()  asm volatile("cp.async.commit_group;\n")
#define CP_WAIT(N)   asm volatile("cp.async.wait_group %0;\n" :: "n"(N))

// ---------------------------------------------------------------------------
// Kernel W: one-time hi/lo tf32 split of W_qkv, stored in pi(k) layout.
// Source float4 k..k+3 (k = 16a+4b) scatters to positions 16a + b + {0,4,8,12}.
// ---------------------------------------------------------------------------
__global__ __launch_bounds__(256) void wsplit_kernel(const float* __restrict__ Wq)
{
    int idx = (blockIdx.x * 256 + threadIdx.x) * 4;
    float4 v = *(const float4*)&Wq[idx];
    float hx = to_tf32(v.x), hy = to_tf32(v.y), hz = to_tf32(v.z), hw = to_tf32(v.w);
    int p0 = (idx & ~15) | ((idx >> 2) & 3);
    g_wh[p0]    = hx;  g_wh[p0+4]  = hy;  g_wh[p0+8]  = hz;  g_wh[p0+12] = hw;
    g_wl[p0]    = to_tf32(v.x-hx);
    g_wl[p0+4]  = to_tf32(v.y-hy);
    g_wl[p0+8]  = to_tf32(v.z-hz);
    g_wl[p0+12] = to_tf32(v.w-hw);
}

// ---------------------------------------------------------------------------
// Kernel A: QKV projection via 3xTF32 compensated mma GEMM.
// Operand roles: A = fmap (m = pos, scalar frags, conflict-free),
// B = W (n = o, pi(k) layout -> float4 frags via cp.async'd swizzled smem).
// Per-chunk LDS: 64 LDS.128 + 64 LDS.32 (was 320 LDS.32).
// ---------------------------------------------------------------------------
__global__ __launch_bounds__(128) void qkv_kernel(
    const float* __restrict__ fmap,
    const float* __restrict__ pf, const float* __restrict__ ph,
    const float* __restrict__ pw)
{
    extern __shared__ float qsm[];
    // [Wh0 0][Wl0 4096][Wh1 8192][Wl1 12288][Bh 16384][Bl 20480]
    float* Bh = qsm + 16384;   // fmap hi: [k][pos ^ ((k&3)<<3)]
    float* Bl = qsm + 20480;
    float* Ts = qsm;           // 64x65 epilogue overlay

    const int tid  = threadIdx.x;
    const int lane = tid & 31, w = tid >> 5;
    const int gid  = lane >> 2, tig = lane & 3;
    const int row0 = w*16 + gid;            // pos-row within tile (m-dim)
    const int pbase = blockIdx.x * 64;
    const int obase = blockIdx.y * 64;
    const int b     = blockIdx.z;
    const int vsw = (gid & 3) << 4;         // W-tile swizzle key
    const int asw = tig << 3;               // fmap A-frag swizzle key
    const int r0 = tid >> 4, c4l = (tid & 15) * 4;
    const uint32_t sbase = (uint32_t)__cvta_generic_to_shared(qsm);

    float acc[8][4];
#pragma unroll
    for (int nb=0;nb<8;nb++)
#pragma unroll
        for (int c=0;c<4;c++) acc[nb][c] = 0.f;

    // cp.async W(ks) -> buffer buf (hi at buf*32768 B, lo at +16384 B)
    auto loadW = [&](int ks, int buf) {
        uint32_t dA = sbase + (uint32_t)buf * 32768u;
#pragma unroll
        for (int p=0;p<8;p++) {
            int r = r0 + p*8;               // o-row 0..63
            uint32_t o = (uint32_t)(r*64 + (c4l ^ ((r&3)<<4))) * 4u;
            cp16(dA + o,          &g_wh[(obase + r)*CIN + ks*64 + c4l], true);
            cp16(dA + 16384u + o, &g_wl[(obase + r)*CIN + ks*64 + c4l], true);
        }
    };

    float4 rb[8];
    loadW(0, 0); CP_COMMIT();
#pragma unroll
    for (int p=0;p<8;p++) {
        int r = r0 + p*8;
        rb[p] = make_float4(0.f,0.f,0.f,0.f);
        if (pbase + c4l < NPOS)
            rb[p] = *(const float4*)&fmap[(size_t)(b*CIN + r)*NPOS + pbase + c4l];
    }

    for (int ks = 0; ks < 4; ks++) {
        // split & store fmap B(ks): [k][pos] with ((k&3)<<3) swizzle
#pragma unroll
        for (int p=0;p<8;p++) {
            int r = r0 + p*8;
            float4 v = rb[p];
            float hx = to_tf32(v.x), hy = to_tf32(v.y), hz = to_tf32(v.z), hw = to_tf32(v.w);
            int o = r*64 + (c4l ^ ((r&3)<<3));
            *(float4*)&Bh[o] = make_float4(hx, hy, hz, hw);
            *(float4*)&Bl[o] = make_float4(to_tf32(v.x-hx), to_tf32(v.y-hy),
                                           to_tf32(v.z-hz), to_tf32(v.w-hw));
        }
        CP_WAIT(0);            // W(ks) resident
        __syncthreads();

        if (ks < 3) {
            loadW(ks+1, (ks+1)&1); CP_COMMIT();
            int kn = (ks+1)*64;
#pragma unroll
            for (int p=0;p<8;p++) {
                int r = r0 + p*8;
                rb[p] = make_float4(0.f,0.f,0.f,0.f);
                if (pbase + c4l < NPOS)
                    rb[p] = *(const float4*)&fmap[(size_t)(b*CIN + kn + r)*NPOS + pbase + c4l];
            }
        }

        const float* Wh = qsm + (ks&1)*8192;
        const float* Wl = Wh + 4096;
#pragma unroll
        for (int kpi=0; kpi<4; kpi++) {
            int kb = kpi*16;
            // fmap A-frags (kc even: k = kb+tig, kb+tig+4; kc odd: +8)
            uint32_t aeh0 = __float_as_uint(Bh[(kb+tig   )*64 + ( row0    ^ asw)]);
            uint32_t aeh1 = __float_as_uint(Bh[(kb+tig   )*64 + ((row0+8) ^ asw)]);
            uint32_t aeh2 = __float_as_uint(Bh[(kb+tig+4 )*64 + ( row0    ^ asw)]);
            uint32_t aeh3 = __float_as_uint(Bh[(kb+tig+4 )*64 + ((row0+8) ^ asw)]);
            uint32_t ael0 = __float_as_uint(Bl[(kb+tig   )*64 + ( row0    ^ asw)]);
            uint32_t ael1 = __float_as_uint(Bl[(kb+tig   )*64 + ((row0+8) ^ asw)]);
            uint32_t ael2 = __float_as_uint(Bl[(kb+tig+4 )*64 + ( row0    ^ asw)]);
            uint32_t ael3 = __float_as_uint(Bl[(kb+tig+4 )*64 + ((row0+8) ^ asw)]);
            uint32_t aoh0 = __float_as_uint(Bh[(kb+tig+8 )*64 + ( row0    ^ asw)]);
            uint32_t aoh1 = __float_as_uint(Bh[(kb+tig+8 )*64 + ((row0+8) ^ asw)]);
            uint32_t aoh2 = __float_as_uint(Bh[(kb+tig+12)*64 + ( row0    ^ asw)]);
            uint32_t aoh3 = __float_as_uint(Bh[(kb+tig+12)*64 + ((row0+8) ^ asw)]);
            uint32_t aol0 = __float_as_uint(Bl[(kb+tig+8 )*64 + ( row0    ^ asw)]);
            uint32_t aol1 = __float_as_uint(Bl[(kb+tig+8 )*64 + ((row0+8) ^ asw)]);
            uint32_t aol2 = __float_as_uint(Bl[(kb+tig+12)*64 + ( row0    ^ asw)]);
            uint32_t aol3 = __float_as_uint(Bl[(kb+tig+12)*64 + ((row0+8) ^ asw)]);
#pragma unroll
            for (int nb=0; nb<8; nb++) {
                int rr = nb*8 + gid;
                float4 wh4 = *(const float4*)&Wh[rr*64 + (kb ^ vsw) + tig*4];
                float4 wl4 = *(const float4*)&Wl[rr*64 + (kb ^ vsw) + tig*4];
                uint32_t whx=__float_as_uint(wh4.x), why=__float_as_uint(wh4.y);
                uint32_t whz=__float_as_uint(wh4.z), whw=__float_as_uint(wh4.w);
                uint32_t wlx=__float_as_uint(wl4.x), wly=__float_as_uint(wl4.y);
                uint32_t wlz=__float_as_uint(wl4.z), wlw=__float_as_uint(wl4.w);
                // kc even: hi*lo, lo*hi, hi*hi
                mma_tf32(acc[nb], aeh0,aeh1,aeh2,aeh3, wlx,wly);
                mma_tf32(acc[nb], ael0,ael1,ael2,ael3, whx,why);
                mma_tf32(acc[nb], aeh0,aeh1,aeh2,aeh3, whx,why);
                // kc odd
                mma_tf32(acc[nb], aoh0,aoh1,aoh2,aoh3, wlz,wlw);
                mma_tf32(acc[nb], aol0,aol1,aol2,aol3, whz,whw);
                mma_tf32(acc[nb], aoh0,aoh1,aoh2,aoh3, whz,whw);
            }
        }
        __syncthreads();
    }

    // scl * log2(e): attention runs in the exp2 domain
    const float scl = 0.08838834764831845f * 1.4426950408889634f;
    const int sec  = obase >> 9;
    const int head = (obase >> 7) & 3;
    const int d0   = obase & 127;
    const int bh   = b*NH + head;

    // c-frag: rows = pos (row0 + half*8), cols = o (nb*8 + 2*tig + e)
    if (sec < 2) {
        // stage direct: Ts[pos][o]
#pragma unroll
        for (int nb=0;nb<8;nb++)
#pragma unroll
            for (int half=0;half<2;half++)
#pragma unroll
                for (int e=0;e<2;e++)
                    Ts[(row0 + half*8)*65 + nb*8 + 2*tig + e] = acc[nb][half*2+e];
    } else {
        // stage transposed: Ts[o][pos]
#pragma unroll
        for (int nb=0;nb<8;nb++)
#pragma unroll
            for (int half=0;half<2;half++)
#pragma unroll
                for (int e=0;e<2;e++)
                    Ts[(nb*8 + 2*tig + e)*65 + row0 + half*8] = acc[nb][half*2+e];
    }
    __syncthreads();

    const int rr  = tid >> 4;
    const int c4  = (tid & 15) * 4;
    const int tq  = (c4 >> 2) & 3;
    const int cb  = c4 & ~15;
    const int lc0 = cb + tq, lc1 = cb + 4 + tq, lc2 = cb + 8 + tq, lc3 = cb + 12 + tq;
    const int lv0 = cb + 2*tq, lv1 = cb + 2*tq + 1, lv2 = cb + 2*tq + 8, lv3 = cb + 2*tq + 9;

#pragma unroll
    for (int pass=0; pass<8; pass++) {
        int r = rr + pass*8;
        if (sec == 2) {
            if (pbase + c4 < NPOS) {
                float v0 = Ts[r*65+lv0], v1 = Ts[r*65+lv1];
                float v2 = Ts[r*65+lv2], v3 = Ts[r*65+lv3];
                *(float4*)&g_v[((size_t)bh*DH + d0 + r)*NPOS + pbase + c4] =
                    make_float4(to_tf32(v0), to_tf32(v1), to_tf32(v2), to_tf32(v3));
            }
        } else {
            float v0 = Ts[r*65+lc0], v1 = Ts[r*65+lc1];
            float v2 = Ts[r*65+lc2], v3 = Ts[r*65+lc3];
            int pos = pbase + r;
            if (pos < NPOS) {
                size_t o_ = ((size_t)bh*NPOS + pos)*DH + d0 + c4;
                if (sec == 0) {
                    *(float4*)&g_q[o_] = make_float4(
                        to_tf32(v0*scl), to_tf32(v1*scl), to_tf32(v2*scl), to_tf32(v3*scl));
                } else {
                    int f_ = pos / 196; int rem = pos - f_*196;
                    int h_ = rem / 14;  int w_  = rem - h_*14;
                    const float* pfr = pf + f_*DH + d0;
                    const float* phr = ph + h_*DH + d0;
                    const float* pwr = pw + w_*DH + d0;
                    *(float4*)&g_k[o_] = make_float4(
                        to_tf32(v0 + pfr[lc0] + phr[lc0] + pwr[lc0]),
                        to_tf32(v1 + pfr[lc1] + phr[lc1] + pwr[lc1]),
                        to_tf32(v2 + pfr[lc2] + phr[lc2] + pwr[lc2]),
                        to_tf32(v3 + pfr[lc3] + phr[lc3] + pwr[lc3]));
                }
            }
        }
    }
}

// ---------------------------------------------------------------------------
// Kernel B: flash attention (round-12 version — best measured).
// Br=128/CTA, 256 threads; fixed-reference-max softmax; S c-frags feed PV
// directly (sigma/rho layout); cp.async double-buffered K + pipelined V.
// ---------------------------------------------------------------------------
__global__ __launch_bounds__(256, 1) void attn_kernel(float* __restrict__ out)
{
    extern __shared__ float sm[];
    float* Kb[2] = { sm, sm + 8192 };
    float* Vb    = sm + 16384;         // [d=128][rho(tok)=64]
    float* Od    = sm;                 // 128 x 132 overlay

    const int tid  = threadIdx.x;
    const int lane = tid & 31, w = tid >> 5;
    const int gid  = lane >> 2, tig = lane & 3;
    const int qt = blockIdx.x, bh = blockIdx.y;
    const int qbase = qt * 128;
    const int row0 = w*16 + gid;
    const int gsw = gid << 4;
    const int vsw = (gid & 3) << 4;

    const float* qp = g_q + (size_t)bh * NPOS * DH;
    const float* kp = g_k + (size_t)bh * NPOS * DH;
    const float* vp = g_v + (size_t)bh * DH * NPOS;

    // ---- Q staging through Kb[0], two 64-row passes ----
    uint32_t qa[16][4];
#pragma unroll
    for (int pass = 0; pass < 2; pass++) {
        int r0 = tid >> 5; int c4 = (tid & 31) * 4;
#pragma unroll
        for (int p=0;p<8;p++) {
            int r = r0 + p*8;
            float4 v = make_float4(0.f,0.f,0.f,0.f);
            int grow = qbase + pass*64 + r;
            if (grow < NPOS) v = *(const float4*)&qp[(size_t)grow*DH + c4];
            *(float4*)&Kb[0][r*128 + (c4 ^ ((r&7)<<4))] = v;
        }
        __syncthreads();
        if ((w >> 2) == pass) {
            int lr = row0 & 63;
#pragma unroll
            for (int kpi=0;kpi<8;kpi++) {
                float4 ra = *(const float4*)&Kb[0][ lr   *128 + ((kpi*16) ^ gsw) + tig*4];
                float4 rb = *(const float4*)&Kb[0][(lr+8)*128 + ((kpi*16) ^ gsw) + tig*4];
                qa[2*kpi  ][0] = __float_as_uint(ra.x); qa[2*kpi  ][1] = __float_as_uint(rb.x);
                qa[2*kpi  ][2] = __float_as_uint(ra.y); qa[2*kpi  ][3] = __float_as_uint(rb.y);
                qa[2*kpi+1][0] = __float_as_uint(ra.z); qa[2*kpi+1][1] = __float_as_uint(rb.z);
                qa[2*kpi+1][2] = __float_as_uint(ra.w); qa[2*kpi+1][3] = __float_as_uint(rb.w);
            }
        }
        __syncthreads();
    }

    const uint32_t smK0 = (uint32_t)__cvta_generic_to_shared(Kb[0]);
    const uint32_t smK1 = (uint32_t)__cvta_generic_to_shared(Kb[1]);
    const uint32_t smV  = (uint32_t)__cvta_generic_to_shared(Vb);
    const int lr0 = tid >> 5, lc4 = (tid & 31) * 4;
    const int vr0 = tid >> 4, vc4 = (tid & 15) * 4;

#pragma unroll
    for (int p=0;p<8;p++) {
        int r = lr0 + p*8;
        cp16(smK0 + (r*128 + (lc4 ^ ((r&7)<<4)))*4, &kp[(size_t)r*DH + lc4], r < NPOS);
    }
    CP_COMMIT();
#pragma unroll
    for (int p=0;p<8;p++) {
        int r = vr0 + p*16;
        cp16(smV + (r*64 + (vc4 ^ ((r&3)<<4)))*4, &vp[(size_t)r*NPOS + vc4], vc4 < NPOS);
    }
    CP_COMMIT();

    float m0 = 0.f, m1 = 0.f;
    float l0 = 0.f, l1 = 0.f;
    float O[16][4];
#pragma unroll
    for (int nb=0;nb<16;nb++)
#pragma unroll
        for (int c=0;c<4;c++) O[nb][c] = 0.f;

    for (int t = 0; t < 25; t++) {
        const int kb = t * 64;
        const float* Ks = Kb[t & 1];
        CP_WAIT(1);
        __syncthreads();

        float S[8][4];
#pragma unroll
        for (int nb=0;nb<8;nb++)
#pragma unroll
            for (int c=0;c<4;c++) S[nb][c] = 0.f;
#pragma unroll
        for (int kpi=0;kpi<8;kpi++) {
#pragma unroll
            for (int nb=0;nb<8;nb++) {
                int rr = nb*8 + gid;
                float4 kv = *(const float4*)&Ks[rr*128 + ((kpi*16) ^ gsw) + tig*4];
                mma_tf32(S[nb], qa[2*kpi  ][0],qa[2*kpi  ][1],qa[2*kpi  ][2],qa[2*kpi  ][3],
                         __float_as_uint(kv.x), __float_as_uint(kv.y));
                mma_tf32(S[nb], qa[2*kpi+1][0],qa[2*kpi+1][1],qa[2*kpi+1][2],qa[2*kpi+1][3],
                         __float_as_uint(kv.z), __float_as_uint(kv.w));
            }
        }

        {   // prefetch K(t+1)
            int tn = (t+1 < 25) ? t+1 : 24;
            const float* kpn = kp + (size_t)tn*64*DH;
            uint32_t dstK = (t & 1) ? smK0 : smK1;
#pragma unroll
            for (int p=0;p<8;p++) {
                int r = lr0 + p*8;
                cp16(dstK + (r*128 + (lc4 ^ ((r&7)<<4)))*4,
                     &kpn[(size_t)r*DH + lc4], tn*64 + r < NPOS);
            }
            CP_COMMIT();
        }

        if (kb + 64 > NPOS) {
#pragma unroll
            for (int nb=0;nb<8;nb++) {
                int c0 = kb + nb*8 + 2*tig;
                if (c0     >= NPOS) { S[nb][0] = -1e30f; S[nb][2] = -1e30f; }
                if (c0 + 1 >= NPOS) { S[nb][1] = -1e30f; S[nb][3] = -1e30f; }
            }
        }

        if (t == 0) {
            float mx0 = -1e30f, mx1 = -1e30f;
#pragma unroll
            for (int nb=0;nb<8;nb++) {
                mx0 = fmaxf(mx0, fmaxf(S[nb][0], S[nb][1]));
                mx1 = fmaxf(mx1, fmaxf(S[nb][2], S[nb][3]));
            }
            mx0 = fmaxf(mx0, __shfl_xor_sync(0xffffffffu, mx0, 1));
            mx0 = fmaxf(mx0, __shfl_xor_sync(0xffffffffu, mx0, 2));
            mx1 = fmaxf(mx1, __shfl_xor_sync(0xffffffffu, mx1, 1));
            mx1 = fmaxf(mx1, __shfl_xor_sync(0xffffffffu, mx1, 2));
            m0 = mx0; m1 = mx1;
        }

        float rs0 = 0.f, rs1 = 0.f;
#pragma unroll
        for (int nb=0;nb<8;nb++) {
            S[nb][0] = fast_exp2(S[nb][0] - m0); rs0 += S[nb][0];
            S[nb][1] = fast_exp2(S[nb][1] - m0); rs0 += S[nb][1];
            S[nb][2] = fast_exp2(S[nb][2] - m1); rs1 += S[nb][2];
            S[nb][3] = fast_exp2(S[nb][3] - m1); rs1 += S[nb][3];
        }
        l0 += rs0;
        l1 += rs1;

        CP_WAIT(1);
        __syncthreads();

        // ---- O += P V : S c-frags ARE the A-frags (sigma/rho layout) ----
#pragma unroll
        for (int kpi=0;kpi<4;kpi++) {
            int e = 2*kpi, o = 2*kpi+1;
            uint32_t ea0 = __float_as_uint(to_tf32(S[e][0]));
            uint32_t ea1 = __float_as_uint(to_tf32(S[e][2]));
            uint32_t ea2 = __float_as_uint(to_tf32(S[e][1]));
            uint32_t ea3 = __float_as_uint(to_tf32(S[e][3]));
            uint32_t oa0 = __float_as_uint(to_tf32(S[o][0]));
            uint32_t oa1 = __float_as_uint(to_tf32(S[o][2]));
            uint32_t oa2 = __float_as_uint(to_tf32(S[o][1]));
            uint32_t oa3 = __float_as_uint(to_tf32(S[o][3]));
#pragma unroll
            for (int nb=0;nb<16;nb++) {
                int rr = nb*8 + gid;
                float4 vv = *(const float4*)&Vb[rr*64 + ((kpi*16) ^ vsw) + tig*4];
                mma_tf32(O[nb], ea0,ea1,ea2,ea3,
                         __float_as_uint(vv.x), __float_as_uint(vv.y));
                mma_tf32(O[nb], oa0,oa1,oa2,oa3,
                         __float_as_uint(vv.z), __float_as_uint(vv.w));
            }
        }
        __syncthreads();

        {   // prefetch V(t+1)
            int tn = (t+1 < 25) ? t+1 : 24;
            const float* vpn = vp + (size_t)tn*64;
#pragma unroll
            for (int p=0;p<8;p++) {
                int r = vr0 + p*16;
                cp16(smV + (r*64 + (vc4 ^ ((r&3)<<4)))*4,
                     &vpn[(size_t)r*NPOS + vc4], tn*64 + vc4 < NPOS);
            }
            CP_COMMIT();
        }
    }

    l0 += __shfl_xor_sync(0xffffffffu, l0, 1);
    l0 += __shfl_xor_sync(0xffffffffu, l0, 2);
    l1 += __shfl_xor_sync(0xffffffffu, l1, 1);
    l1 += __shfl_xor_sync(0xffffffffu, l1, 2);

    CP_WAIT(0);
    __syncthreads();
    float inv0 = 1.0f / l0, inv1 = 1.0f / l1;
#pragma unroll
    for (int nb=0;nb<16;nb++) {
        Od[(nb*8 + 2*tig    )*132 + row0    ] = O[nb][0] * inv0;
        Od[(nb*8 + 2*tig + 1)*132 + row0    ] = O[nb][1] * inv0;
        Od[(nb*8 + 2*tig    )*132 + row0 + 8] = O[nb][2] * inv1;
        Od[(nb*8 + 2*tig + 1)*132 + row0 + 8] = O[nb][3] * inv1;
    }
    __syncthreads();

    const int b = bh >> 2, head = bh & 3;
    const size_t ch0 = (size_t)b*512 + head*128;
    {
        int t2 = (tid & 63) * 2;
#pragma unroll
        for (int p=0;p<32;p++) {
            int dd = (tid >> 6) + p*4;
            if (qbase + t2 < NPOS) {
                float2 v = *(const float2*)&Od[dd*132 + t2];
                *(float2*)&out[(ch0 + dd)*NPOS + qbase + t2] = v;
            }
        }
    }
}

// ---------------------------------------------------------------------------
extern "C" void kernel_launch(void* const* d_in, const int* in_sizes, int n_in,
                              void* d_out, int out_size)
{
    const float* fmap = (const float*)d_in[0];
    const float* Wq   = (const float*)d_in[1];
    const float* pf   = (const float*)d_in[2];
    const float* ph   = (const float*)d_in[3];
    const float* pw   = (const float*)d_in[4];
    float* out = (float*)d_out;

    wsplit_kernel<<<O3*CIN/1024, 256>>>(Wq);

    const size_t smemA = (size_t)24576 * sizeof(float);   // 96 KB
    cudaFuncSetAttribute(qkv_kernel, cudaFuncAttributeMaxDynamicSharedMemorySize,
                         (int)smemA);
    dim3 gA(25, 24, BATCH);
    qkv_kernel<<<gA, 128, smemA>>>(fmap, pf, ph, pw);

    const size_t smemB = (size_t)24576 * sizeof(float);   // 96 KB
    cudaFuncSetAttribute(attn_kernel, cudaFuncAttributeMaxDynamicSharedMemorySize,
                         (int)smemB);
    dim3 gB(13, 32);
    attn_kernel<<<gB, 256, smemB>>>(out);
}